// round 3
// baseline (speedup 1.0000x reference)
#include <cuda_runtime.h>
#include <cstdint>

// SSIM loss: pred/target (16,3,512,512) fp32, 11x11 gaussian (sigma=1.5)
// depthwise conv, zero padding, out = 1 - mean(ssim_map).
// Single fused kernel: separable conv (vertical f32x2 pass -> horizontal
// f32x2 pass), per-pixel SSIM, block reduce, last-block finalize.

#define HH 512
#define WW 512
#define PLANE (HH * WW)
#define NC 48
#define TILE_W 64
#define TILE_H 32
#define SH 42                  // TILE_H + 10
#define SWD 74                 // TILE_W + 10
#define SPITCH 76              // input tile pitch (even, LDS.64-aligned)
#define IMPITCH 78             // intermediate pitch (even; 14*r mod 32 perm -> conflict-free)
#define IM_PLANE (TILE_H * IMPITCH)
#define GRID_X 8               // 512/64
#define GRID_Y 16              // 512/32
#define NBLOCKS (GRID_X * GRID_Y * NC)   // 6144
#define NPIX (16.0 * 3.0 * 512.0 * 512.0)

#define SP_OFF 0
#define ST_OFF (SH * SPITCH)
#define IM_OFF (2 * SH * SPITCH)
#define SMEM_FLOATS (IM_OFF + 5 * IM_PLANE)   // 6384 + 12480 = 18864
#define SMEM_BYTES (SMEM_FLOATS * 4)          // 75456 (2 blocks = 151KB <= 228KB)

// gaussian(11, sigma=1.5), normalized
#define W0 0.001028380f
#define W1 0.007598758f
#define W2 0.036000773f
#define W3 0.109360702f
#define W4 0.213005530f
#define W5 0.266011730f

__device__ float g_accum;            // zero at module load; reset by last block
__device__ unsigned int g_count;     // zero at module load; reset by last block

__device__ __forceinline__ float wt(int k) {
    switch (k) {
        case 0:  return W0;
        case 1:  return W1;
        case 2:  return W2;
        case 3:  return W3;
        case 4:  return W4;
        case 5:  return W5;
        case 6:  return W4;
        case 7:  return W3;
        case 8:  return W2;
        case 9:  return W1;
        default: return W0;
    }
}

// ---- packed f32x2 helpers (sm_103a) ----
__device__ __forceinline__ uint64_t pk2(float lo, float hi) {
    uint64_t r;
    asm("mov.b64 %0, {%1, %2};" : "=l"(r) : "f"(lo), "f"(hi));
    return r;
}
__device__ __forceinline__ void upk2(float& lo, float& hi, uint64_t v) {
    asm("mov.b64 {%0, %1}, %2;" : "=f"(lo), "=f"(hi) : "l"(v));
}
__device__ __forceinline__ uint64_t mul2(uint64_t a, uint64_t b) {
    uint64_t d;
    asm("mul.rn.f32x2 %0, %1, %2;" : "=l"(d) : "l"(a), "l"(b));
    return d;
}
__device__ __forceinline__ void fma2(uint64_t& d, uint64_t a, uint64_t b) {
    asm("fma.rn.f32x2 %0, %1, %2, %0;" : "+l"(d) : "l"(a), "l"(b));
}
__device__ __forceinline__ uint64_t wpair(int k) {
    float w = wt(k);
    return pk2(w, w);   // ptxas CSEs the 6 unique values
}

__global__ void __launch_bounds__(256, 2) ssim_main(
    const float* __restrict__ pred, const float* __restrict__ targ,
    float* __restrict__ out)
{
    extern __shared__ float smem[];
    float* sp = smem + SP_OFF;
    float* st = smem + ST_OFF;
    float* im = smem + IM_OFF;   // 5 planes of IM_PLANE floats
    __shared__ float wsum[8];

    const int tid = threadIdx.x;
    const int z = blockIdx.z;
    const float* __restrict__ pbase = pred + (size_t)z * PLANE;
    const float* __restrict__ tbase = targ + (size_t)z * PLANE;
    const int gx0 = blockIdx.x * TILE_W - 5;
    const int gy0 = blockIdx.y * TILE_H - 5;

    // ---- load halo tile (zero pad) ----
    for (int i = tid; i < SH * SWD; i += 256) {
        int r = i / SWD;
        int c = i - r * SWD;
        int gr = gy0 + r;
        int gc = gx0 + c;
        float pv = 0.f, tv = 0.f;
        if ((unsigned)gr < (unsigned)HH && (unsigned)gc < (unsigned)WW) {
            size_t off = (size_t)gr * WW + gc;
            pv = pbase[off];
            tv = tbase[off];
        }
        sp[r * SPITCH + c] = pv;
        st[r * SPITCH + c] = tv;
    }
    __syncthreads();

    // ---- vertical pass (packed over column pairs) ----
    // 37 column pairs x 8 row groups (4 rows each) = 296 tasks
    for (int t = tid; t < 37 * 8; t += 256) {
        const int cp = t % 37;
        const int rg = t / 37;
        const int r0 = rg * 4;
        const int cb = 2 * cp;          // even -> 8B aligned

        uint64_t ax[4], ay[4], axx[4], ayy[4], axy[4];
        #pragma unroll
        for (int o = 0; o < 4; ++o) { ax[o]=0; ay[o]=0; axx[o]=0; ayy[o]=0; axy[o]=0; }

        const float* sprow = sp + cb;
        const float* strow = st + cb;
        #pragma unroll
        for (int rr = 0; rr < 14; ++rr) {
            uint64_t P = *(const uint64_t*)&sprow[(r0 + rr) * SPITCH];
            uint64_t Q = *(const uint64_t*)&strow[(r0 + rr) * SPITCH];
            uint64_t PP = mul2(P, P);
            uint64_t QQ = mul2(Q, Q);
            uint64_t PQ = mul2(P, Q);
            #pragma unroll
            for (int o = 0; o < 4; ++o) {
                const int k = rr - o;
                if (k >= 0 && k < 11) {
                    const uint64_t w = wpair(k);
                    fma2(ax[o],  w, P);
                    fma2(ay[o],  w, Q);
                    fma2(axx[o], w, PP);
                    fma2(ayy[o], w, QQ);
                    fma2(axy[o], w, PQ);
                }
            }
        }
        #pragma unroll
        for (int o = 0; o < 4; ++o) {
            const int base = (r0 + o) * IMPITCH + cb;   // even -> 8B aligned
            *(uint64_t*)&im[0*IM_PLANE + base] = ax[o];
            *(uint64_t*)&im[1*IM_PLANE + base] = ay[o];
            *(uint64_t*)&im[2*IM_PLANE + base] = axx[o];
            *(uint64_t*)&im[3*IM_PLANE + base] = ayy[o];
            *(uint64_t*)&im[4*IM_PLANE + base] = axy[o];
        }
    }
    __syncthreads();

    // ---- horizontal pass + SSIM ----
    // lane = output row (0..31), warp = column group of 8 (4 output pairs)
    float lsum = 0.f;
    {
        const int r  = tid & 31;
        const int c0 = (tid >> 5) * 8;
        const int rbase = r * IMPITCH + c0;   // even -> 8B aligned

        uint64_t acc[5][4];
        #pragma unroll
        for (int m = 0; m < 5; ++m)
            #pragma unroll
            for (int j = 0; j < 4; ++j) acc[m][j] = 0;

        // stream one map at a time to bound live registers
        #pragma unroll
        for (int m = 0; m < 5; ++m) {
            uint64_t e[9];      // even-aligned input pairs (v0,v1)..(v16,v17)
            #pragma unroll
            for (int i = 0; i < 9; ++i)
                e[i] = *(const uint64_t*)&im[m * IM_PLANE + rbase + 2 * i];
            uint64_t od[8];     // crossed pairs (v1,v2)..(v15,v16)
            #pragma unroll
            for (int i = 0; i < 8; ++i) {
                float lo0, hi0, lo1, hi1;
                upk2(lo0, hi0, e[i]);
                upk2(lo1, hi1, e[i + 1]);
                od[i] = pk2(hi0, lo1);
            }
            #pragma unroll
            for (int j = 0; j < 4; ++j) {
                #pragma unroll
                for (int k = 0; k < 11; ++k) {
                    const int s = k + 2 * j;
                    const uint64_t pr = (s & 1) ? od[(s - 1) >> 1] : e[s >> 1];
                    fma2(acc[m][j], wpair(k), pr);
                }
            }
        }

        const float C1 = 1e-4f;
        const float C2 = 9e-4f;
        #pragma unroll
        for (int j = 0; j < 4; ++j) {
            float mx[2], my[2], exx[2], eyy[2], exy[2];
            upk2(mx[0],  mx[1],  acc[0][j]);
            upk2(my[0],  my[1],  acc[1][j]);
            upk2(exx[0], exx[1], acc[2][j]);
            upk2(eyy[0], eyy[1], acc[3][j]);
            upk2(exy[0], exy[1], acc[4][j]);
            #pragma unroll
            for (int h = 0; h < 2; ++h) {
                float mxx = mx[h] * mx[h];
                float myy = my[h] * my[h];
                float mxy = mx[h] * my[h];
                float vx  = exx[h] - mxx;
                float vy  = eyy[h] - myy;
                float vxy = exy[h] - mxy;
                float num = fmaf(2.f, mxy, C1) * fmaf(2.f, vxy, C2);
                float den = (mxx + myy + C1) * (vx + vy + C2);
                lsum += __fdividef(num, den);
            }
        }
    }

    // ---- block reduction ----
    #pragma unroll
    for (int s = 16; s > 0; s >>= 1)
        lsum += __shfl_xor_sync(0xffffffffu, lsum, s);
    if ((tid & 31) == 0) wsum[tid >> 5] = lsum;
    __syncthreads();

    // ---- global accumulate + last-block finalize ----
    if (tid == 0) {
        float bs = 0.f;
        #pragma unroll
        for (int i = 0; i < 8; ++i) bs += wsum[i];
        atomicAdd(&g_accum, bs);
        __threadfence();
        unsigned int prev = atomicAdd(&g_count, 1u);
        if (prev == NBLOCKS - 1) {
            float s = g_accum;
            out[0] = (float)(1.0 - (double)s / NPIX);
            g_accum = 0.f;          // reset for next graph replay
            g_count = 0u;
        }
    }
}

extern "C" void kernel_launch(void* const* d_in, const int* in_sizes, int n_in,
                              void* d_out, int out_size)
{
    (void)in_sizes; (void)n_in; (void)out_size;
    const float* pred = (const float*)d_in[0];
    const float* targ = (const float*)d_in[1];

    cudaFuncSetAttribute(ssim_main,
                         cudaFuncAttributeMaxDynamicSharedMemorySize, SMEM_BYTES);

    dim3 grid(GRID_X, GRID_Y, NC);
    ssim_main<<<grid, 256, SMEM_BYTES>>>(pred, targ, (float*)d_out);
}

// round 4
// speedup vs baseline: 1.0460x; 1.0460x over previous
#include <cuda_runtime.h>
#include <cstdint>

// SSIM loss: pred/target (16,3,512,512) fp32, 11x11 gaussian (sigma=1.5)
// depthwise conv, zero padding, out = 1 - mean(ssim_map).
// Single fused kernel: separable conv (vertical f32x2 pass -> horizontal
// f32x2 pass), per-pixel SSIM, block reduce, last-block finalize.
// Tile 64x16, 4 blocks/SM for latency hiding.

#define HH 512
#define WW 512
#define PLANE (HH * WW)
#define NC 48
#define TILE_W 64
#define TILE_H 16
#define SH 26                  // TILE_H + 10
#define SWD 74                 // TILE_W + 10
#define SPITCH 76              // input tile pitch (even, LDS.64-aligned)
#define IMPITCH 78             // intermediate pitch (78 mod 32 = 14 -> conflict-free phases)
#define IM_PLANE (TILE_H * IMPITCH)
#define GRID_X 8               // 512/64
#define GRID_Y 32              // 512/16
#define NBLOCKS (GRID_X * GRID_Y * NC)   // 12288
#define NPIX (16.0 * 3.0 * 512.0 * 512.0)

#define SP_OFF 0
#define ST_OFF (SH * SPITCH)
#define IM_OFF (2 * SH * SPITCH)          // 3952 floats
#define SMEM_FLOATS (IM_OFF + 5 * IM_PLANE)   // 3952 + 6240 = 10192
#define SMEM_BYTES (SMEM_FLOATS * 4)          // 40768 (<48KB, 4+/SM)

// gaussian(11, sigma=1.5), normalized
#define W0 0.001028380f
#define W1 0.007598758f
#define W2 0.036000773f
#define W3 0.109360702f
#define W4 0.213005530f
#define W5 0.266011730f

__device__ float g_accum;            // zero at module load; reset by last block
__device__ unsigned int g_count;     // zero at module load; reset by last block

__device__ __forceinline__ float wt(int k) {
    switch (k) {
        case 0:  return W0;
        case 1:  return W1;
        case 2:  return W2;
        case 3:  return W3;
        case 4:  return W4;
        case 5:  return W5;
        case 6:  return W4;
        case 7:  return W3;
        case 8:  return W2;
        case 9:  return W1;
        default: return W0;
    }
}

// ---- packed f32x2 helpers (sm_103a) ----
__device__ __forceinline__ uint64_t pk2(float lo, float hi) {
    uint64_t r;
    asm("mov.b64 %0, {%1, %2};" : "=l"(r) : "f"(lo), "f"(hi));
    return r;
}
__device__ __forceinline__ void upk2(float& lo, float& hi, uint64_t v) {
    asm("mov.b64 {%0, %1}, %2;" : "=f"(lo), "=f"(hi) : "l"(v));
}
__device__ __forceinline__ uint64_t mul2(uint64_t a, uint64_t b) {
    uint64_t d;
    asm("mul.rn.f32x2 %0, %1, %2;" : "=l"(d) : "l"(a), "l"(b));
    return d;
}
__device__ __forceinline__ void fma2(uint64_t& d, uint64_t a, uint64_t b) {
    asm("fma.rn.f32x2 %0, %1, %2, %0;" : "+l"(d) : "l"(a), "l"(b));
}
__device__ __forceinline__ uint64_t wpair(int k) {
    float w = wt(k);
    return pk2(w, w);   // ptxas CSEs the 6 unique values
}

__global__ void __launch_bounds__(256, 4) ssim_main(
    const float* __restrict__ pred, const float* __restrict__ targ,
    float* __restrict__ out)
{
    extern __shared__ float smem[];
    float* sp = smem + SP_OFF;
    float* st = smem + ST_OFF;
    float* im = smem + IM_OFF;   // 5 planes of IM_PLANE floats
    __shared__ float wsum[8];

    const int tid = threadIdx.x;
    const int z = blockIdx.z;
    const float* __restrict__ pbase = pred + (size_t)z * PLANE;
    const float* __restrict__ tbase = targ + (size_t)z * PLANE;
    const int gx0 = blockIdx.x * TILE_W - 5;
    const int gy0 = blockIdx.y * TILE_H - 5;

    // ---- load halo tile (zero pad), 26x74 x 2 arrays ----
    for (int i = tid; i < SH * SWD; i += 256) {
        int r = i / SWD;
        int c = i - r * SWD;
        int gr = gy0 + r;
        int gc = gx0 + c;
        float pv = 0.f, tv = 0.f;
        if ((unsigned)gr < (unsigned)HH && (unsigned)gc < (unsigned)WW) {
            size_t off = (size_t)gr * WW + gc;
            pv = pbase[off];
            tv = tbase[off];
        }
        sp[r * SPITCH + c] = pv;
        st[r * SPITCH + c] = tv;
    }
    __syncthreads();

    // ---- vertical pass (packed over column pairs) ----
    // 37 column pairs x 4 row groups (4 rows each) = 148 tasks, ONE round
    if (tid < 37 * 4) {
        const int cp = tid % 37;
        const int rg = tid / 37;
        const int r0 = rg * 4;
        const int cb = 2 * cp;          // even -> 8B aligned

        uint64_t ax[4], ay[4], axx[4], ayy[4], axy[4];
        #pragma unroll
        for (int o = 0; o < 4; ++o) { ax[o]=0; ay[o]=0; axx[o]=0; ayy[o]=0; axy[o]=0; }

        const float* sprow = sp + cb;
        const float* strow = st + cb;
        #pragma unroll
        for (int rr = 0; rr < 14; ++rr) {
            uint64_t P = *(const uint64_t*)&sprow[(r0 + rr) * SPITCH];
            uint64_t Q = *(const uint64_t*)&strow[(r0 + rr) * SPITCH];
            uint64_t PP = mul2(P, P);
            uint64_t QQ = mul2(Q, Q);
            uint64_t PQ = mul2(P, Q);
            #pragma unroll
            for (int o = 0; o < 4; ++o) {
                const int k = rr - o;
                if (k >= 0 && k < 11) {
                    const uint64_t w = wpair(k);
                    fma2(ax[o],  w, P);
                    fma2(ay[o],  w, Q);
                    fma2(axx[o], w, PP);
                    fma2(ayy[o], w, QQ);
                    fma2(axy[o], w, PQ);
                }
            }
        }
        #pragma unroll
        for (int o = 0; o < 4; ++o) {
            const int base = (r0 + o) * IMPITCH + cb;   // even -> 8B aligned
            *(uint64_t*)&im[0*IM_PLANE + base] = ax[o];
            *(uint64_t*)&im[1*IM_PLANE + base] = ay[o];
            *(uint64_t*)&im[2*IM_PLANE + base] = axx[o];
            *(uint64_t*)&im[3*IM_PLANE + base] = ayy[o];
            *(uint64_t*)&im[4*IM_PLANE + base] = axy[o];
        }
    }
    __syncthreads();

    // ---- horizontal pass + SSIM ----
    // 16 rows x 16 col-groups (4 cols = 2 output pairs) = exactly 256 tasks.
    // Lane remap keeps each 16-lane LDS.64 phase conflict-free:
    //   half-warp spans 8 col-groups x 2 rows; banks {4cg} U {14+4cg}.
    float lsum = 0.f;
    {
        const int w = tid >> 5;
        const int l = tid & 31;
        const int row = 2 * w + ((l >> 3) & 1);
        const int cg  = (l & 7) | ((l >> 4) << 3);
        const int c0 = 4 * cg;
        const int rbase = row * IMPITCH + c0;   // even -> 8B aligned

        uint64_t acc[5][2];
        #pragma unroll
        for (int m = 0; m < 5; ++m) { acc[m][0] = 0; acc[m][1] = 0; }

        // stream one map at a time to bound live registers
        #pragma unroll
        for (int m = 0; m < 5; ++m) {
            uint64_t e[7];      // even-aligned input pairs, cols c0..c0+13
            #pragma unroll
            for (int i = 0; i < 7; ++i)
                e[i] = *(const uint64_t*)&im[m * IM_PLANE + rbase + 2 * i];
            uint64_t od[6];     // crossed pairs (v1,v2)..(v11,v12)
            #pragma unroll
            for (int i = 0; i < 6; ++i) {
                float lo0, hi0, lo1, hi1;
                upk2(lo0, hi0, e[i]);
                upk2(lo1, hi1, e[i + 1]);
                od[i] = pk2(hi0, lo1);
            }
            #pragma unroll
            for (int j = 0; j < 2; ++j) {
                #pragma unroll
                for (int k = 0; k < 11; ++k) {
                    const int s = k + 2 * j;
                    const uint64_t pr = (s & 1) ? od[(s - 1) >> 1] : e[s >> 1];
                    fma2(acc[m][j], wpair(k), pr);
                }
            }
        }

        const float C1 = 1e-4f;
        const float C2 = 9e-4f;
        #pragma unroll
        for (int j = 0; j < 2; ++j) {
            float mx[2], my[2], exx[2], eyy[2], exy[2];
            upk2(mx[0],  mx[1],  acc[0][j]);
            upk2(my[0],  my[1],  acc[1][j]);
            upk2(exx[0], exx[1], acc[2][j]);
            upk2(eyy[0], eyy[1], acc[3][j]);
            upk2(exy[0], exy[1], acc[4][j]);
            #pragma unroll
            for (int h = 0; h < 2; ++h) {
                float mxx = mx[h] * mx[h];
                float myy = my[h] * my[h];
                float mxy = mx[h] * my[h];
                float vx  = exx[h] - mxx;
                float vy  = eyy[h] - myy;
                float vxy = exy[h] - mxy;
                float num = fmaf(2.f, mxy, C1) * fmaf(2.f, vxy, C2);
                float den = (mxx + myy + C1) * (vx + vy + C2);
                lsum += __fdividef(num, den);
            }
        }
    }

    // ---- block reduction ----
    #pragma unroll
    for (int s = 16; s > 0; s >>= 1)
        lsum += __shfl_xor_sync(0xffffffffu, lsum, s);
    if ((tid & 31) == 0) wsum[tid >> 5] = lsum;
    __syncthreads();

    // ---- global accumulate + last-block finalize ----
    if (tid == 0) {
        float bs = 0.f;
        #pragma unroll
        for (int i = 0; i < 8; ++i) bs += wsum[i];
        atomicAdd(&g_accum, bs);
        __threadfence();
        unsigned int prev = atomicAdd(&g_count, 1u);
        if (prev == NBLOCKS - 1) {
            float s = g_accum;
            out[0] = (float)(1.0 - (double)s / NPIX);
            g_accum = 0.f;          // reset for next graph replay
            g_count = 0u;
        }
    }
}

extern "C" void kernel_launch(void* const* d_in, const int* in_sizes, int n_in,
                              void* d_out, int out_size)
{
    (void)in_sizes; (void)n_in; (void)out_size;
    const float* pred = (const float*)d_in[0];
    const float* targ = (const float*)d_in[1];

    dim3 grid(GRID_X, GRID_Y, NC);
    ssim_main<<<grid, 256, SMEM_BYTES>>>(pred, targ, (float*)d_out);
}

// round 5
// speedup vs baseline: 1.1770x; 1.1253x over previous
#include <cuda_runtime.h>
#include <cstdint>

// SSIM loss: pred/target (16,3,512,512) fp32, 11x11 gaussian (sigma=1.5)
// depthwise conv, zero padding, out = 1 - mean(ssim_map).
// Single fused kernel, tile 64x16, 256 thr, 5 blocks/SM (regs<=48 by design):
//   v-pass in two map-groups (caps accumulator regs), h-pass rolling-pair
//   f32x2 streaming, per-pixel SSIM, block reduce, last-block finalize.

#define HH 512
#define WW 512
#define PLANE (HH * WW)
#define NC 48
#define TILE_W 64
#define TILE_H 16
#define SH 26                  // TILE_H + 10
#define SWD 74                 // TILE_W + 10
#define SPITCH 76              // input tile pitch (even, LDS.64-aligned)
#define IMPITCH 78             // intermediate pitch (mod 32 = 14 -> conflict-free)
#define IM_PLANE (TILE_H * IMPITCH)
#define GRID_X 8               // 512/64
#define GRID_Y 32              // 512/16
#define NBLOCKS (GRID_X * GRID_Y * NC)   // 12288
#define NPIX (16.0 * 3.0 * 512.0 * 512.0)

#define SP_OFF 0
#define ST_OFF (SH * SPITCH)
#define IM_OFF (2 * SH * SPITCH)              // 3952 floats
#define SMEM_FLOATS (IM_OFF + 5 * IM_PLANE)   // 10192
#define SMEM_BYTES (SMEM_FLOATS * 4)          // 40768 B -> 5 blocks/SM by smem

// gaussian(11, sigma=1.5), normalized
#define W0 0.001028380f
#define W1 0.007598758f
#define W2 0.036000773f
#define W3 0.109360702f
#define W4 0.213005530f
#define W5 0.266011730f

__device__ float g_accum;            // zero at module load; reset by last block
__device__ unsigned int g_count;     // zero at module load; reset by last block

__device__ __forceinline__ float wt(int k) {
    switch (k) {
        case 0:  return W0;
        case 1:  return W1;
        case 2:  return W2;
        case 3:  return W3;
        case 4:  return W4;
        case 5:  return W5;
        case 6:  return W4;
        case 7:  return W3;
        case 8:  return W2;
        case 9:  return W1;
        default: return W0;
    }
}

// ---- packed f32x2 helpers (sm_103a) ----
__device__ __forceinline__ uint64_t pk2(float lo, float hi) {
    uint64_t r;
    asm("mov.b64 %0, {%1, %2};" : "=l"(r) : "f"(lo), "f"(hi));
    return r;
}
__device__ __forceinline__ void upk2(float& lo, float& hi, uint64_t v) {
    asm("mov.b64 {%0, %1}, %2;" : "=f"(lo), "=f"(hi) : "l"(v));
}
__device__ __forceinline__ uint64_t mul2(uint64_t a, uint64_t b) {
    uint64_t d;
    asm("mul.rn.f32x2 %0, %1, %2;" : "=l"(d) : "l"(a), "l"(b));
    return d;
}
__device__ __forceinline__ void fma2(uint64_t& d, uint64_t a, uint64_t b) {
    asm("fma.rn.f32x2 %0, %1, %2, %0;" : "+l"(d) : "l"(a), "l"(b));
}
__device__ __forceinline__ uint64_t wpair(int k) {
    float w = wt(k);
    return pk2(w, w);   // ptxas CSEs the 6 unique values
}

__global__ void __launch_bounds__(256, 5) ssim_main(
    const float* __restrict__ pred, const float* __restrict__ targ,
    float* __restrict__ out)
{
    extern __shared__ float smem[];
    float* sp = smem + SP_OFF;
    float* st = smem + ST_OFF;
    float* im = smem + IM_OFF;   // 5 planes of IM_PLANE floats
    __shared__ float wsum[8];

    const int tid = threadIdx.x;
    const int z = blockIdx.z;
    const float* __restrict__ pbase = pred + (size_t)z * PLANE;
    const float* __restrict__ tbase = targ + (size_t)z * PLANE;
    const int gx0 = blockIdx.x * TILE_W - 5;
    const int gy0 = blockIdx.y * TILE_H - 5;

    // ---- load halo tile (zero pad), 26x74 x 2 arrays ----
    for (int i = tid; i < SH * SWD; i += 256) {
        int r = i / SWD;
        int c = i - r * SWD;
        int gr = gy0 + r;
        int gc = gx0 + c;
        float pv = 0.f, tv = 0.f;
        if ((unsigned)gr < (unsigned)HH && (unsigned)gc < (unsigned)WW) {
            size_t off = (size_t)gr * WW + gc;
            pv = pbase[off];
            tv = tbase[off];
        }
        sp[r * SPITCH + c] = pv;
        st[r * SPITCH + c] = tv;
    }
    __syncthreads();

    // ---- vertical pass (packed over column pairs), two map-groups ----
    // 37 column pairs x 4 row groups (4 rows each) = 148 tasks.
    if (tid < 37 * 4) {
        const int cp = tid % 37;
        const int rg = tid / 37;
        const int r0 = rg * 4;
        const int cb = 2 * cp;          // even -> 8B aligned
        const float* sprow = sp + r0 * SPITCH + cb;
        const float* strow = st + r0 * SPITCH + cb;
        const int obase = (r0) * IMPITCH + cb;

        // -- group A: x, y, xy (12 u64 accumulators) --
        {
            uint64_t ax[4], ay[4], axy[4];
            #pragma unroll
            for (int o = 0; o < 4; ++o) { ax[o]=0; ay[o]=0; axy[o]=0; }
            #pragma unroll
            for (int rr = 0; rr < 14; ++rr) {
                uint64_t P = *(const uint64_t*)&sprow[rr * SPITCH];
                uint64_t Q = *(const uint64_t*)&strow[rr * SPITCH];
                uint64_t PQ = mul2(P, Q);
                #pragma unroll
                for (int o = 0; o < 4; ++o) {
                    const int k = rr - o;
                    if (k >= 0 && k < 11) {
                        const uint64_t w = wpair(k);
                        fma2(ax[o],  w, P);
                        fma2(ay[o],  w, Q);
                        fma2(axy[o], w, PQ);
                    }
                }
            }
            #pragma unroll
            for (int o = 0; o < 4; ++o) {
                *(uint64_t*)&im[0*IM_PLANE + obase + o*IMPITCH] = ax[o];
                *(uint64_t*)&im[1*IM_PLANE + obase + o*IMPITCH] = ay[o];
                *(uint64_t*)&im[4*IM_PLANE + obase + o*IMPITCH] = axy[o];
            }
        }
        // -- group B: xx, yy (8 u64 accumulators) --
        {
            uint64_t axx[4], ayy[4];
            #pragma unroll
            for (int o = 0; o < 4; ++o) { axx[o]=0; ayy[o]=0; }
            #pragma unroll
            for (int rr = 0; rr < 14; ++rr) {
                uint64_t P = *(const uint64_t*)&sprow[rr * SPITCH];
                uint64_t Q = *(const uint64_t*)&strow[rr * SPITCH];
                uint64_t PP = mul2(P, P);
                uint64_t QQ = mul2(Q, Q);
                #pragma unroll
                for (int o = 0; o < 4; ++o) {
                    const int k = rr - o;
                    if (k >= 0 && k < 11) {
                        const uint64_t w = wpair(k);
                        fma2(axx[o], w, PP);
                        fma2(ayy[o], w, QQ);
                    }
                }
            }
            #pragma unroll
            for (int o = 0; o < 4; ++o) {
                *(uint64_t*)&im[2*IM_PLANE + obase + o*IMPITCH] = axx[o];
                *(uint64_t*)&im[3*IM_PLANE + obase + o*IMPITCH] = ayy[o];
            }
        }
    }
    __syncthreads();

    // ---- horizontal pass + SSIM (rolling-pair streaming, low regs) ----
    // 16 rows x 16 col-groups (4 cols = 2 output pairs) = exactly 256 tasks.
    // Lane remap keeps each 16-lane LDS.64 phase conflict-free.
    float lsum = 0.f;
    {
        const int w = tid >> 5;
        const int l = tid & 31;
        const int row = 2 * w + ((l >> 3) & 1);
        const int cg  = (l & 7) | ((l >> 4) << 3);
        const int rbase = row * IMPITCH + 4 * cg;   // even -> 8B aligned

        float res[5][4];

        #pragma unroll
        for (int m = 0; m < 5; ++m) {
            uint64_t acc0 = 0, acc1 = 0;   // output pairs (c0,c0+1), (c0+2,c0+3)
            uint64_t eprev = 0;
            #pragma unroll
            for (int i = 0; i < 7; ++i) {
                uint64_t ecur = *(const uint64_t*)&im[m * IM_PLANE + rbase + 2 * i];
                if (i > 0) {
                    float h0, l1, dump;
                    upk2(dump, h0, eprev);
                    upk2(l1, dump, ecur);
                    uint64_t od = pk2(h0, l1);      // (v_{2i-1}, v_{2i})
                    if (2*i - 1 <= 10) fma2(acc0, wpair(2*i - 1), od);
                    if (2*i - 3 >= 0)  fma2(acc1, wpair(2*i - 3), od);
                }
                if (2*i <= 10)              fma2(acc0, wpair(2*i), ecur);
                if (2*i - 2 >= 0)           fma2(acc1, wpair(2*i - 2), ecur);
                eprev = ecur;
            }
            upk2(res[m][0], res[m][1], acc0);
            upk2(res[m][2], res[m][3], acc1);
        }

        const float C1 = 1e-4f;
        const float C2 = 9e-4f;
        #pragma unroll
        for (int h = 0; h < 4; ++h) {
            float mx  = res[0][h], my  = res[1][h];
            float exx = res[2][h], eyy = res[3][h], exy = res[4][h];
            float mxx = mx * mx;
            float myy = my * my;
            float mxy = mx * my;
            float vx  = exx - mxx;
            float vy  = eyy - myy;
            float vxy = exy - mxy;
            float num = fmaf(2.f, mxy, C1) * fmaf(2.f, vxy, C2);
            float den = (mxx + myy + C1) * (vx + vy + C2);
            lsum += __fdividef(num, den);
        }
    }

    // ---- block reduction ----
    #pragma unroll
    for (int s = 16; s > 0; s >>= 1)
        lsum += __shfl_xor_sync(0xffffffffu, lsum, s);
    if ((tid & 31) == 0) wsum[tid >> 5] = lsum;
    __syncthreads();

    // ---- global accumulate + last-block finalize ----
    if (tid == 0) {
        float bs = 0.f;
        #pragma unroll
        for (int i = 0; i < 8; ++i) bs += wsum[i];
        atomicAdd(&g_accum, bs);
        __threadfence();
        unsigned int prev = atomicAdd(&g_count, 1u);
        if (prev == NBLOCKS - 1) {
            float s = g_accum;
            out[0] = (float)(1.0 - (double)s / NPIX);
            g_accum = 0.f;          // reset for next graph replay
            g_count = 0u;
        }
    }
}

extern "C" void kernel_launch(void* const* d_in, const int* in_sizes, int n_in,
                              void* d_out, int out_size)
{
    (void)in_sizes; (void)n_in; (void)out_size;
    const float* pred = (const float*)d_in[0];
    const float* targ = (const float*)d_in[1];

    dim3 grid(GRID_X, GRID_Y, NC);
    ssim_main<<<grid, 256, SMEM_BYTES>>>(pred, targ, (float*)d_out);
}

// round 6
// speedup vs baseline: 1.3345x; 1.1338x over previous
#include <cuda_runtime.h>
#include <cstdint>

// SSIM loss: pred/target (16,3,512,512) fp32, 11x11 gaussian (sigma=1.5)
// depthwise conv, zero padding, out = 1 - mean(ssim_map).
// Single fused kernel, tile 64x16, 256 thr, 5 blocks/SM.
// R6: v-pass map-groups parallelized across threads (304 tasks), float2 halo.

#define HH 512
#define WW 512
#define PLANE (HH * WW)
#define NC 48
#define TILE_W 64
#define TILE_H 16
#define SH 26                  // TILE_H + 10
#define NPAIRS 38              // halo column pairs (76 cols, pair-aligned frame)
#define SPITCH 78              // input tile pitch (even)
#define IMPITCH 78             // intermediate pitch (mod 32 = 14 -> conflict-free)
#define IM_PLANE (TILE_H * IMPITCH)
#define GRID_X 8               // 512/64
#define GRID_Y 32              // 512/16
#define NBLOCKS (GRID_X * GRID_Y * NC)   // 12288
#define NPIX (16.0 * 3.0 * 512.0 * 512.0)

#define SP_OFF 0
#define ST_OFF (SH * SPITCH)
#define IM_OFF (2 * SH * SPITCH)              // 4056 floats
#define SMEM_FLOATS (IM_OFF + 5 * IM_PLANE)   // 10296
#define SMEM_BYTES (SMEM_FLOATS * 4)          // 41184 B -> 5 blocks/SM

// v-pass task split: 152 group-A tasks + 152 group-B tasks
#define NVT_A (NPAIRS * 4)     // 152
#define NVT_ALL (2 * NVT_A)    // 304

// gaussian(11, sigma=1.5), normalized
#define W0 0.001028380f
#define W1 0.007598758f
#define W2 0.036000773f
#define W3 0.109360702f
#define W4 0.213005530f
#define W5 0.266011730f

__device__ float g_accum;            // zero at module load; reset by last block
__device__ unsigned int g_count;     // zero at module load; reset by last block

__device__ __forceinline__ float wt(int k) {
    switch (k) {
        case 0:  return W0;
        case 1:  return W1;
        case 2:  return W2;
        case 3:  return W3;
        case 4:  return W4;
        case 5:  return W5;
        case 6:  return W4;
        case 7:  return W3;
        case 8:  return W2;
        case 9:  return W1;
        default: return W0;
    }
}

// ---- packed f32x2 helpers (sm_103a) ----
__device__ __forceinline__ uint64_t pk2(float lo, float hi) {
    uint64_t r;
    asm("mov.b64 %0, {%1, %2};" : "=l"(r) : "f"(lo), "f"(hi));
    return r;
}
__device__ __forceinline__ void upk2(float& lo, float& hi, uint64_t v) {
    asm("mov.b64 {%0, %1}, %2;" : "=f"(lo), "=f"(hi) : "l"(v));
}
__device__ __forceinline__ float lo2(uint64_t v) { float a, b; upk2(a, b, v); return a; }
__device__ __forceinline__ float hi2(uint64_t v) { float a, b; upk2(a, b, v); return b; }
__device__ __forceinline__ uint64_t mul2(uint64_t a, uint64_t b) {
    uint64_t d;
    asm("mul.rn.f32x2 %0, %1, %2;" : "=l"(d) : "l"(a), "l"(b));
    return d;
}
__device__ __forceinline__ void fma2(uint64_t& d, uint64_t a, uint64_t b) {
    asm("fma.rn.f32x2 %0, %1, %2, %0;" : "+l"(d) : "l"(a), "l"(b));
}
__device__ __forceinline__ uint64_t wpair(int k) {
    float w = wt(k);
    return pk2(w, w);   // ptxas CSEs the 6 unique values
}

// One v-pass task: group A (x, y, xy) or group B (xx, yy) for a column pair.
__device__ __forceinline__ void vtask(int id, const float* sp, const float* st,
                                      float* im)
{
    const bool isA = (id < NVT_A);
    const int t = isA ? id : id - NVT_A;
    const int cp = t % NPAIRS;
    const int rg = t / NPAIRS;
    const int r0 = rg * 4;
    const int cb = 2 * cp;                 // even -> 8B aligned
    const float* sprow = sp + r0 * SPITCH + cb;
    const float* strow = st + r0 * SPITCH + cb;
    const int obase = r0 * IMPITCH + cb;

    if (isA) {
        uint64_t ax[4], ay[4], axy[4];
        #pragma unroll
        for (int o = 0; o < 4; ++o) { ax[o]=0; ay[o]=0; axy[o]=0; }
        #pragma unroll
        for (int rr = 0; rr < 14; ++rr) {
            uint64_t P = *(const uint64_t*)&sprow[rr * SPITCH];
            uint64_t Q = *(const uint64_t*)&strow[rr * SPITCH];
            uint64_t PQ = mul2(P, Q);
            #pragma unroll
            for (int o = 0; o < 4; ++o) {
                const int k = rr - o;
                if (k >= 0 && k < 11) {
                    const uint64_t w = wpair(k);
                    fma2(ax[o],  w, P);
                    fma2(ay[o],  w, Q);
                    fma2(axy[o], w, PQ);
                }
            }
        }
        #pragma unroll
        for (int o = 0; o < 4; ++o) {
            *(uint64_t*)&im[0*IM_PLANE + obase + o*IMPITCH] = ax[o];
            *(uint64_t*)&im[1*IM_PLANE + obase + o*IMPITCH] = ay[o];
            *(uint64_t*)&im[4*IM_PLANE + obase + o*IMPITCH] = axy[o];
        }
    } else {
        uint64_t axx[4], ayy[4];
        #pragma unroll
        for (int o = 0; o < 4; ++o) { axx[o]=0; ayy[o]=0; }
        #pragma unroll
        for (int rr = 0; rr < 14; ++rr) {
            uint64_t P = *(const uint64_t*)&sprow[rr * SPITCH];
            uint64_t Q = *(const uint64_t*)&strow[rr * SPITCH];
            uint64_t PP = mul2(P, P);
            uint64_t QQ = mul2(Q, Q);
            #pragma unroll
            for (int o = 0; o < 4; ++o) {
                const int k = rr - o;
                if (k >= 0 && k < 11) {
                    const uint64_t w = wpair(k);
                    fma2(axx[o], w, PP);
                    fma2(ayy[o], w, QQ);
                }
            }
        }
        #pragma unroll
        for (int o = 0; o < 4; ++o) {
            *(uint64_t*)&im[2*IM_PLANE + obase + o*IMPITCH] = axx[o];
            *(uint64_t*)&im[3*IM_PLANE + obase + o*IMPITCH] = ayy[o];
        }
    }
}

__global__ void __launch_bounds__(256, 5) ssim_main(
    const float* __restrict__ pred, const float* __restrict__ targ,
    float* __restrict__ out)
{
    extern __shared__ float smem[];
    float* sp = smem + SP_OFF;
    float* st = smem + ST_OFF;
    float* im = smem + IM_OFF;   // 5 planes of IM_PLANE floats
    __shared__ float wsum[8];

    const int tid = threadIdx.x;
    const int z = blockIdx.z;
    const float* __restrict__ pbase = pred + (size_t)z * PLANE;
    const float* __restrict__ tbase = targ + (size_t)z * PLANE;
    const int gx0 = blockIdx.x * TILE_W - 6;   // even -> float2-aligned frame
    const int gy0 = blockIdx.y * TILE_H - 5;

    // ---- load halo tile as float2 pairs (zero pad) ----
    // smem col s corresponds to gc = gx0 + s; pairs never straddle the edge.
    for (int i = tid; i < SH * NPAIRS; i += 256) {
        int r = i / NPAIRS;
        int pp = i - r * NPAIRS;
        int gr = gy0 + r;
        int gc = gx0 + 2 * pp;
        float2 pv = make_float2(0.f, 0.f);
        float2 tv = make_float2(0.f, 0.f);
        if ((unsigned)gr < (unsigned)HH && (unsigned)gc < (unsigned)WW) {
            size_t off = (size_t)gr * WW + gc;
            pv = *(const float2*)(pbase + off);
            tv = *(const float2*)(tbase + off);
        }
        *(float2*)&sp[r * SPITCH + 2 * pp] = pv;
        *(float2*)&st[r * SPITCH + 2 * pp] = tv;
    }
    __syncthreads();

    // ---- vertical pass: 304 tasks (152 A + 152 B) over 256 threads ----
    vtask(tid, sp, st, im);
    if (tid < NVT_ALL - 256)
        vtask(256 + tid, sp, st, im);
    __syncthreads();

    // ---- horizontal pass + SSIM (rolling-pair streaming) ----
    // Output col j (tile frame) reads im s = j+1 .. j+11 (s = gc - gx0).
    // 16 rows x 16 col-groups (4 cols = 2 output pairs) = exactly 256 tasks.
    float lsum = 0.f;
    {
        const int w = tid >> 5;
        const int l = tid & 31;
        const int row = 2 * w + ((l >> 3) & 1);
        const int cg  = (l & 7) | ((l >> 4) << 3);
        const int c0 = 4 * cg;
        const int rbase = row * IMPITCH + c0;   // even -> 8B aligned

        float res[5][4];

        #pragma unroll
        for (int m = 0; m < 5; ++m) {
            uint64_t acc0 = 0, acc1 = 0;   // pairs (c0,c0+1), (c0+2,c0+3)
            uint64_t eprev = 0;
            #pragma unroll
            for (int i = 0; i < 8; ++i) {
                uint64_t ecur = *(const uint64_t*)&im[m * IM_PLANE + rbase + 2 * i];
                if (i > 0) {
                    // od_{i-1}: pair starting at s = c0 + 2i - 1
                    uint64_t od = pk2(hi2(eprev), lo2(ecur));
                    if (i - 1 <= 5)            fma2(acc0, wpair(2*i - 2), od);
                    if (i >= 2 && i - 1 <= 6)  fma2(acc1, wpair(2*i - 4), od);
                }
                // e_i: pair starting at s = c0 + 2i
                if (i >= 1 && i <= 5)          fma2(acc0, wpair(2*i - 1), ecur);
                if (i >= 2 && i <= 6)          fma2(acc1, wpair(2*i - 3), ecur);
                eprev = ecur;
            }
            upk2(res[m][0], res[m][1], acc0);
            upk2(res[m][2], res[m][3], acc1);
        }

        const float C1 = 1e-4f;
        const float C2 = 9e-4f;
        #pragma unroll
        for (int h = 0; h < 4; ++h) {
            float mx  = res[0][h], my  = res[1][h];
            float exx = res[2][h], eyy = res[3][h], exy = res[4][h];
            float mxx = mx * mx;
            float myy = my * my;
            float mxy = mx * my;
            float vx  = exx - mxx;
            float vy  = eyy - myy;
            float vxy = exy - mxy;
            float num = fmaf(2.f, mxy, C1) * fmaf(2.f, vxy, C2);
            float den = (mxx + myy + C1) * (vx + vy + C2);
            lsum += __fdividef(num, den);
        }
    }

    // ---- block reduction ----
    #pragma unroll
    for (int s = 16; s > 0; s >>= 1)
        lsum += __shfl_xor_sync(0xffffffffu, lsum, s);
    if ((tid & 31) == 0) wsum[tid >> 5] = lsum;
    __syncthreads();

    // ---- global accumulate + last-block finalize ----
    if (tid == 0) {
        float bs = 0.f;
        #pragma unroll
        for (int i = 0; i < 8; ++i) bs += wsum[i];
        atomicAdd(&g_accum, bs);
        __threadfence();
        unsigned int prev = atomicAdd(&g_count, 1u);
        if (prev == NBLOCKS - 1) {
            float s = g_accum;
            out[0] = (float)(1.0 - (double)s / NPIX);
            g_accum = 0.f;          // reset for next graph replay
            g_count = 0u;
        }
    }
}

extern "C" void kernel_launch(void* const* d_in, const int* in_sizes, int n_in,
                              void* d_out, int out_size)
{
    (void)in_sizes; (void)n_in; (void)out_size;
    const float* pred = (const float*)d_in[0];
    const float* targ = (const float*)d_in[1];

    dim3 grid(GRID_X, GRID_Y, NC);
    ssim_main<<<grid, 256, SMEM_BYTES>>>(pred, targ, (float*)d_out);
}

// round 7
// speedup vs baseline: 1.4521x; 1.0881x over previous
#include <cuda_runtime.h>
#include <cstdint>

// SSIM loss: pred/target (16,3,512,512) fp32, 11x11 gaussian (sigma=1.5)
// depthwise conv, zero padding, out = 1 - mean(ssim_map).
// Single fused kernel, tile 64x16, 256 thr, 5 blocks/SM.
// R7: unified o=2 v-pass (each input read once), float4 halo, pitch 80/78.

#define HH 512
#define WW 512
#define PLANE (HH * WW)
#define NC 48
#define TILE_W 64
#define TILE_H 16
#define SH 26                  // TILE_H + 10
#define SPITCH 80              // input tile pitch (16B-aligned rows)
#define NQUADS 20              // float4 quads per halo row (80 cols)
#define IMPITCH 78             // intermediate pitch (odd bankpair row-term -> conflict-free)
#define IM_PLANE (TILE_H * IMPITCH)
#define GRID_X 8               // 512/64
#define GRID_Y 32              // 512/16
#define NBLOCKS (GRID_X * GRID_Y * NC)   // 12288
#define NPIX (16.0 * 3.0 * 512.0 * 512.0)

#define SP_OFF 0
#define ST_OFF (SH * SPITCH)                  // 2080 floats
#define IM_OFF (2 * SH * SPITCH)              // 4160 floats
#define SMEM_FLOATS (IM_OFF + 5 * IM_PLANE)   // 4160 + 6240 = 10400
#define SMEM_BYTES (SMEM_FLOATS * 4)          // 41600 B -> 5 blocks/SM

// v-pass: column pairs p = 1..38 (im cols s=2..77), 8 row-groups of 2 rows
#define NVT (38 * 8)           // 304 tasks

// gaussian(11, sigma=1.5), normalized
#define W0 0.001028380f
#define W1 0.007598758f
#define W2 0.036000773f
#define W3 0.109360702f
#define W4 0.213005530f
#define W5 0.266011730f

__device__ float g_accum;            // zero at module load; reset by last block
__device__ unsigned int g_count;     // zero at module load; reset by last block

__device__ __forceinline__ float wt(int k) {
    switch (k) {
        case 0:  return W0;
        case 1:  return W1;
        case 2:  return W2;
        case 3:  return W3;
        case 4:  return W4;
        case 5:  return W5;
        case 6:  return W4;
        case 7:  return W3;
        case 8:  return W2;
        case 9:  return W1;
        default: return W0;
    }
}

// ---- packed f32x2 helpers (sm_103a) ----
__device__ __forceinline__ uint64_t pk2(float lo, float hi) {
    uint64_t r;
    asm("mov.b64 %0, {%1, %2};" : "=l"(r) : "f"(lo), "f"(hi));
    return r;
}
__device__ __forceinline__ void upk2(float& lo, float& hi, uint64_t v) {
    asm("mov.b64 {%0, %1}, %2;" : "=f"(lo), "=f"(hi) : "l"(v));
}
__device__ __forceinline__ float lo2(uint64_t v) { float a, b; upk2(a, b, v); return a; }
__device__ __forceinline__ float hi2(uint64_t v) { float a, b; upk2(a, b, v); return b; }
__device__ __forceinline__ uint64_t mul2(uint64_t a, uint64_t b) {
    uint64_t d;
    asm("mul.rn.f32x2 %0, %1, %2;" : "=l"(d) : "l"(a), "l"(b));
    return d;
}
__device__ __forceinline__ void fma2(uint64_t& d, uint64_t a, uint64_t b) {
    asm("fma.rn.f32x2 %0, %1, %2, %0;" : "+l"(d) : "l"(a), "l"(b));
}
__device__ __forceinline__ uint64_t wpair(int k) {
    float w = wt(k);
    return pk2(w, w);   // ptxas CSEs the 6 unique values
}

// One v-pass task: ALL 5 maps, 2 output rows, one column pair.
// Reads 12 rows of sp+st exactly once.
__device__ __forceinline__ void vtask(int t, const float* sp, float* im)
{
    const int p  = 1 + (t % 38);
    const int rg = t / 38;             // 0..7
    const int r0 = 2 * rg;
    const float* base = sp + r0 * SPITCH + 2 * p;   // st at +ST_OFF (const fold)

    uint64_t X[2]  = {0, 0}, Y[2]  = {0, 0};
    uint64_t XX[2] = {0, 0}, YY[2] = {0, 0}, XY[2] = {0, 0};

    #pragma unroll
    for (int rr = 0; rr < 12; ++rr) {
        uint64_t P = *(const uint64_t*)&base[rr * SPITCH];
        uint64_t Q = *(const uint64_t*)&base[rr * SPITCH + ST_OFF];
        uint64_t PQ = mul2(P, Q);
        uint64_t PP = mul2(P, P);
        uint64_t QQ = mul2(Q, Q);
        #pragma unroll
        for (int o = 0; o < 2; ++o) {
            const int k = rr - o;
            if (k >= 0 && k < 11) {
                const uint64_t w = wpair(k);
                fma2(X[o],  w, P);
                fma2(Y[o],  w, Q);
                fma2(XX[o], w, PP);
                fma2(YY[o], w, QQ);
                fma2(XY[o], w, PQ);
            }
        }
    }
    const int obase = r0 * IMPITCH + 2 * p;
    #pragma unroll
    for (int o = 0; o < 2; ++o) {
        *(uint64_t*)&im[0*IM_PLANE + obase + o*IMPITCH] = X[o];
        *(uint64_t*)&im[1*IM_PLANE + obase + o*IMPITCH] = Y[o];
        *(uint64_t*)&im[2*IM_PLANE + obase + o*IMPITCH] = XX[o];
        *(uint64_t*)&im[3*IM_PLANE + obase + o*IMPITCH] = YY[o];
        *(uint64_t*)&im[4*IM_PLANE + obase + o*IMPITCH] = XY[o];
    }
}

__global__ void __launch_bounds__(256, 5) ssim_main(
    const float* __restrict__ pred, const float* __restrict__ targ,
    float* __restrict__ out)
{
    extern __shared__ float smem[];
    float* sp = smem + SP_OFF;
    float* st = smem + ST_OFF;
    float* im = smem + IM_OFF;   // 5 planes of IM_PLANE floats, pitch 78
    __shared__ float wsum[8];

    const int tid = threadIdx.x;
    const int z = blockIdx.z;
    const float* __restrict__ pbase = pred + (size_t)z * PLANE;
    const float* __restrict__ tbase = targ + (size_t)z * PLANE;
    const int gx0 = blockIdx.x * TILE_W - 8;   // 16B-aligned frame (mult of 8)
    const int gy0 = blockIdx.y * TILE_H - 5;

    // ---- load halo tile as float4 quads (zero pad); quads never straddle ----
    for (int i = tid; i < SH * NQUADS; i += 256) {
        int r = i / NQUADS;
        int q = i - r * NQUADS;
        int gr = gy0 + r;
        int gc = gx0 + 4 * q;
        float4 pv = make_float4(0.f, 0.f, 0.f, 0.f);
        float4 tv = make_float4(0.f, 0.f, 0.f, 0.f);
        if ((unsigned)gr < (unsigned)HH && (unsigned)gc < (unsigned)WW) {
            size_t off = (size_t)gr * WW + gc;
            pv = *(const float4*)(pbase + off);
            tv = *(const float4*)(tbase + off);
        }
        *(float4*)&sp[r * SPITCH + 4 * q] = pv;
        *(float4*)&st[r * SPITCH + 4 * q] = tv;
    }
    __syncthreads();

    // ---- vertical pass: 304 unified tasks over 256 threads ----
    vtask(tid, sp, im);
    if (tid < NVT - 256)
        vtask(256 + tid, sp, im);
    __syncthreads();

    // ---- horizontal pass + SSIM (rolling-pair streaming) ----
    // Output col j (tile frame): taps at im col s = j+3+k, k=0..10.
    // 16 rows x 16 col-groups (4 cols = 2 output pairs) = exactly 256 tasks.
    float lsum = 0.f;
    {
        const int w = tid >> 5;
        const int l = tid & 31;
        const int row = 2 * w + ((l >> 3) & 1);
        const int cg  = (l & 7) | ((l >> 4) << 3);
        const int j0 = 4 * cg;
        const int rbase = row * IMPITCH + j0 + 2;   // even -> 8B aligned

        float res[5][4];

        #pragma unroll
        for (int m = 0; m < 5; ++m) {
            uint64_t acc0 = 0, acc1 = 0;   // outputs (j0,j0+1), (j0+2,j0+3)
            uint64_t eprev = 0;
            #pragma unroll
            for (int i = 0; i < 8; ++i) {
                uint64_t ecur = *(const uint64_t*)&im[m * IM_PLANE + rbase + 2 * i];
                if (i > 0) {
                    // od_{i-1}: pair starting at s = j0+1+2i
                    uint64_t od = pk2(hi2(eprev), lo2(ecur));
                    if (i <= 6)            fma2(acc0, wpair(2*i - 2), od);
                    if (i >= 2)            fma2(acc1, wpair(2*i - 4), od);
                }
                // e_i: pair starting at s = j0+2+2i
                if (i >= 1 && i <= 5)      fma2(acc0, wpair(2*i - 1), ecur);
                if (i >= 2 && i <= 6)      fma2(acc1, wpair(2*i - 3), ecur);
                eprev = ecur;
            }
            upk2(res[m][0], res[m][1], acc0);
            upk2(res[m][2], res[m][3], acc1);
        }

        const float C1 = 1e-4f;
        const float C2 = 9e-4f;
        #pragma unroll
        for (int h = 0; h < 4; ++h) {
            float mx  = res[0][h], my  = res[1][h];
            float exx = res[2][h], eyy = res[3][h], exy = res[4][h];
            float mxx = mx * mx;
            float myy = my * my;
            float mxy = mx * my;
            float vx  = exx - mxx;
            float vy  = eyy - myy;
            float vxy = exy - mxy;
            float num = fmaf(2.f, mxy, C1) * fmaf(2.f, vxy, C2);
            float den = (mxx + myy + C1) * (vx + vy + C2);
            lsum += __fdividef(num, den);
        }
    }

    // ---- block reduction ----
    #pragma unroll
    for (int s = 16; s > 0; s >>= 1)
        lsum += __shfl_xor_sync(0xffffffffu, lsum, s);
    if ((tid & 31) == 0) wsum[tid >> 5] = lsum;
    __syncthreads();

    // ---- global accumulate + last-block finalize ----
    if (tid == 0) {
        float bs = 0.f;
        #pragma unroll
        for (int i = 0; i < 8; ++i) bs += wsum[i];
        atomicAdd(&g_accum, bs);
        __threadfence();
        unsigned int prev = atomicAdd(&g_count, 1u);
        if (prev == NBLOCKS - 1) {
            float s = g_accum;
            out[0] = (float)(1.0 - (double)s / NPIX);
            g_accum = 0.f;          // reset for next graph replay
            g_count = 0u;
        }
    }
}

extern "C" void kernel_launch(void* const* d_in, const int* in_sizes, int n_in,
                              void* d_out, int out_size)
{
    (void)in_sizes; (void)n_in; (void)out_size;
    const float* pred = (const float*)d_in[0];
    const float* targ = (const float*)d_in[1];

    dim3 grid(GRID_X, GRID_Y, NC);
    ssim_main<<<grid, 256, SMEM_BYTES>>>(pred, targ, (float*)d_out);
}

// round 8
// speedup vs baseline: 1.6003x; 1.1020x over previous
#include <cuda_runtime.h>
#include <cstdint>

// SSIM loss: pred/target (16,3,512,512) fp32, 11x11 gaussian (sigma=1.5)
// depthwise conv, zero padding, out = 1 - mean(ssim_map).
// R8: 4-map formulation (S=x+y, D=x-y, S^2, D^2) -- exact algebraic rewrite:
//   2mu_xy=(A^2-B^2)/2, mu_x^2+mu_y^2=(A^2+B^2)/2,
//   2sg_xy=(C-Dm-(A^2-B^2))/2, sg_x+sg_y=(C+Dm-(A^2+B^2))/2.
// Tile 64x16, 256 thr, 5 blocks/SM, f32x2 packed math throughout.

#define HH 512
#define WW 512
#define PLANE (HH * WW)
#define NC 48
#define TILE_W 64
#define TILE_H 16
#define SH 26                  // TILE_H + 10
#define SPITCH 80              // input tile pitch (16B-aligned rows)
#define NQUADS 20              // float4 quads per halo row (80 cols)
#define IMPITCH 78             // intermediate pitch (conflict-free h-pass phases)
#define IM_PLANE (TILE_H * IMPITCH)
#define NMAPS 4
#define GRID_X 8               // 512/64
#define GRID_Y 32              // 512/16
#define NBLOCKS (GRID_X * GRID_Y * NC)   // 12288
#define NPIX (16.0 * 3.0 * 512.0 * 512.0)

#define SS_OFF 0
#define SD_OFF (SH * SPITCH)                      // 2080 floats
#define IM_OFF (2 * SH * SPITCH)                  // 4160 floats
#define SMEM_FLOATS (IM_OFF + NMAPS * IM_PLANE)   // 4160 + 4992 = 9152
#define SMEM_BYTES (SMEM_FLOATS * 4)              // 36608 B -> 5 blocks/SM

// v-pass: column pairs p = 1..38 (im cols s=2..77), 8 row-groups of 2 rows
#define NVT (38 * 8)           // 304 tasks

// gaussian(11, sigma=1.5), normalized
#define W0 0.001028380f
#define W1 0.007598758f
#define W2 0.036000773f
#define W3 0.109360702f
#define W4 0.213005530f
#define W5 0.266011730f

__device__ float g_accum;            // zero at module load; reset by last block
__device__ unsigned int g_count;     // zero at module load; reset by last block

__device__ __forceinline__ float wt(int k) {
    switch (k) {
        case 0:  return W0;
        case 1:  return W1;
        case 2:  return W2;
        case 3:  return W3;
        case 4:  return W4;
        case 5:  return W5;
        case 6:  return W4;
        case 7:  return W3;
        case 8:  return W2;
        case 9:  return W1;
        default: return W0;
    }
}

// ---- packed f32x2 helpers (sm_103a) ----
__device__ __forceinline__ uint64_t pk2(float lo, float hi) {
    uint64_t r;
    asm("mov.b64 %0, {%1, %2};" : "=l"(r) : "f"(lo), "f"(hi));
    return r;
}
__device__ __forceinline__ void upk2(float& lo, float& hi, uint64_t v) {
    asm("mov.b64 {%0, %1}, %2;" : "=f"(lo), "=f"(hi) : "l"(v));
}
__device__ __forceinline__ float lo2(uint64_t v) { float a, b; upk2(a, b, v); return a; }
__device__ __forceinline__ float hi2(uint64_t v) { float a, b; upk2(a, b, v); return b; }
__device__ __forceinline__ uint64_t mul2(uint64_t a, uint64_t b) {
    uint64_t d;
    asm("mul.rn.f32x2 %0, %1, %2;" : "=l"(d) : "l"(a), "l"(b));
    return d;
}
__device__ __forceinline__ void fma2(uint64_t& d, uint64_t a, uint64_t b) {
    asm("fma.rn.f32x2 %0, %1, %2, %0;" : "+l"(d) : "l"(a), "l"(b));
}
__device__ __forceinline__ uint64_t wpair(int k) {
    float w = wt(k);
    return pk2(w, w);   // ptxas CSEs the 6 unique values
}

// One v-pass task: 4 maps (A=conv S, B=conv D, C=conv S^2, Dm=conv D^2),
// 2 output rows, one column pair. Reads 12 rows of ss+sd exactly once.
__device__ __forceinline__ void vtask(int t, const float* ss, float* im)
{
    const int p  = 1 + (t % 38);
    const int rg = t / 38;             // 0..7
    const int r0 = 2 * rg;
    const float* base = ss + r0 * SPITCH + 2 * p;   // sd at +SD_OFF

    uint64_t mA[2] = {0, 0}, mB[2] = {0, 0};
    uint64_t mC[2] = {0, 0}, mD[2] = {0, 0};

    #pragma unroll
    for (int rr = 0; rr < 12; ++rr) {
        uint64_t S = *(const uint64_t*)&base[rr * SPITCH];
        uint64_t D = *(const uint64_t*)&base[rr * SPITCH + SD_OFF];
        uint64_t S2 = mul2(S, S);
        uint64_t D2 = mul2(D, D);
        #pragma unroll
        for (int o = 0; o < 2; ++o) {
            const int k = rr - o;
            if (k >= 0 && k < 11) {
                const uint64_t w = wpair(k);
                fma2(mA[o], w, S);
                fma2(mB[o], w, D);
                fma2(mC[o], w, S2);
                fma2(mD[o], w, D2);
            }
        }
    }
    const int obase = r0 * IMPITCH + 2 * p;
    #pragma unroll
    for (int o = 0; o < 2; ++o) {
        *(uint64_t*)&im[0*IM_PLANE + obase + o*IMPITCH] = mA[o];
        *(uint64_t*)&im[1*IM_PLANE + obase + o*IMPITCH] = mB[o];
        *(uint64_t*)&im[2*IM_PLANE + obase + o*IMPITCH] = mC[o];
        *(uint64_t*)&im[3*IM_PLANE + obase + o*IMPITCH] = mD[o];
    }
}

__global__ void __launch_bounds__(256, 5) ssim_main(
    const float* __restrict__ pred, const float* __restrict__ targ,
    float* __restrict__ out)
{
    extern __shared__ float smem[];
    float* ss = smem + SS_OFF;   // S = pred + targ  (halo tile)
    float* sd = smem + SD_OFF;   // D = pred - targ
    float* im = smem + IM_OFF;   // 4 planes of IM_PLANE floats, pitch 78
    __shared__ float wsum[8];

    const int tid = threadIdx.x;
    const int z = blockIdx.z;
    const float* __restrict__ pbase = pred + (size_t)z * PLANE;
    const float* __restrict__ tbase = targ + (size_t)z * PLANE;
    const int gx0 = blockIdx.x * TILE_W - 8;   // 16B-aligned frame
    const int gy0 = blockIdx.y * TILE_H - 5;

    // ---- load halo tile as float4 quads, store S/D (zero pad) ----
    for (int i = tid; i < SH * NQUADS; i += 256) {
        int r = i / NQUADS;
        int q = i - r * NQUADS;
        int gr = gy0 + r;
        int gc = gx0 + 4 * q;
        float4 sv = make_float4(0.f, 0.f, 0.f, 0.f);
        float4 dv = make_float4(0.f, 0.f, 0.f, 0.f);
        if ((unsigned)gr < (unsigned)HH && (unsigned)gc < (unsigned)WW) {
            size_t off = (size_t)gr * WW + gc;
            float4 pv = *(const float4*)(pbase + off);
            float4 tv = *(const float4*)(tbase + off);
            sv = make_float4(pv.x + tv.x, pv.y + tv.y, pv.z + tv.z, pv.w + tv.w);
            dv = make_float4(pv.x - tv.x, pv.y - tv.y, pv.z - tv.z, pv.w - tv.w);
        }
        *(float4*)&ss[r * SPITCH + 4 * q] = sv;
        *(float4*)&sd[r * SPITCH + 4 * q] = dv;
    }
    __syncthreads();

    // ---- vertical pass: 304 tasks over 256 threads ----
    vtask(tid, ss, im);
    if (tid < NVT - 256)
        vtask(256 + tid, ss, im);
    __syncthreads();

    // ---- horizontal pass + SSIM (rolling-pair streaming) ----
    // Output col j (tile frame): taps at im col s = j+3+k, k=0..10.
    // 16 rows x 16 col-groups (4 cols = 2 output pairs) = exactly 256 tasks.
    float lsum = 0.f;
    {
        const int w = tid >> 5;
        const int l = tid & 31;
        const int row = 2 * w + ((l >> 3) & 1);
        const int cg  = (l & 7) | ((l >> 4) << 3);
        const int j0 = 4 * cg;
        const int rbase = row * IMPITCH + j0 + 2;   // even -> 8B aligned

        float res[NMAPS][4];

        #pragma unroll
        for (int m = 0; m < NMAPS; ++m) {
            uint64_t acc0 = 0, acc1 = 0;   // outputs (j0,j0+1), (j0+2,j0+3)
            uint64_t eprev = 0;
            #pragma unroll
            for (int i = 0; i < 8; ++i) {
                uint64_t ecur = *(const uint64_t*)&im[m * IM_PLANE + rbase + 2 * i];
                if (i > 0) {
                    // od_{i-1}: pair starting at s = j0+1+2i
                    uint64_t od = pk2(hi2(eprev), lo2(ecur));
                    if (i <= 6)            fma2(acc0, wpair(2*i - 2), od);
                    if (i >= 2)            fma2(acc1, wpair(2*i - 4), od);
                }
                // e_i: pair starting at s = j0+2+2i
                if (i >= 1 && i <= 5)      fma2(acc0, wpair(2*i - 1), ecur);
                if (i >= 2 && i <= 6)      fma2(acc1, wpair(2*i - 3), ecur);
                eprev = ecur;
            }
            upk2(res[m][0], res[m][1], acc0);
            upk2(res[m][2], res[m][3], acc1);
        }

        const float C1 = 1e-4f;
        const float C2 = 9e-4f;
        #pragma unroll
        for (int h = 0; h < 4; ++h) {
            float A  = res[0][h], B  = res[1][h];
            float Cm = res[2][h], Dm = res[3][h];
            float A2 = A * A;
            float B2 = B * B;
            float U  = A2 - B2;           // = 4 mu_xy
            float V  = A2 + B2;           // = 2 (mu_x^2 + mu_y^2)
            float n1 = fmaf(0.5f, U, C1);               // 2 mu_xy + C1
            float n2 = fmaf(0.5f, (Cm - Dm) - U, C2);   // 2 sg_xy + C2
            float d1 = fmaf(0.5f, V, C1);               // mu_x^2+mu_y^2 + C1
            float d2 = fmaf(0.5f, (Cm + Dm) - V, C2);   // sg_x+sg_y + C2
            lsum += __fdividef(n1 * n2, d1 * d2);
        }
    }

    // ---- block reduction ----
    #pragma unroll
    for (int s = 16; s > 0; s >>= 1)
        lsum += __shfl_xor_sync(0xffffffffu, lsum, s);
    if ((tid & 31) == 0) wsum[tid >> 5] = lsum;
    __syncthreads();

    // ---- global accumulate + last-block finalize ----
    if (tid == 0) {
        float bs = 0.f;
        #pragma unroll
        for (int i = 0; i < 8; ++i) bs += wsum[i];
        atomicAdd(&g_accum, bs);
        __threadfence();
        unsigned int prev = atomicAdd(&g_count, 1u);
        if (prev == NBLOCKS - 1) {
            float s = g_accum;
            out[0] = (float)(1.0 - (double)s / NPIX);
            g_accum = 0.f;          // reset for next graph replay
            g_count = 0u;
        }
    }
}

extern "C" void kernel_launch(void* const* d_in, const int* in_sizes, int n_in,
                              void* d_out, int out_size)
{
    (void)in_sizes; (void)n_in; (void)out_size;
    const float* pred = (const float*)d_in[0];
    const float* targ = (const float*)d_in[1];

    dim3 grid(GRID_X, GRID_Y, NC);
    ssim_main<<<grid, 256, SMEM_BYTES>>>(pred, targ, (float*)d_out);
}

// round 9
// speedup vs baseline: 1.6111x; 1.0067x over previous
#include <cuda_runtime.h>
#include <cstdint>

// SSIM loss: pred/target (16,3,512,512) fp32, 11x11 gaussian (sigma=1.5)
// depthwise conv, zero padding, out = 1 - mean(ssim_map).
// R9: same 4-map formulation as R8 (S=x+y, D=x-y, S^2, D^2), but 6 blocks/SM
// (regs 42*256*6 = 64512 <= 64K, smem 36.6KB*6 = 219.6KB <= 227KB).

#define HH 512
#define WW 512
#define PLANE (HH * WW)
#define NC 48
#define TILE_W 64
#define TILE_H 16
#define SH 26                  // TILE_H + 10
#define SPITCH 80              // input tile pitch (16B-aligned rows)
#define NQUADS 20              // float4 quads per halo row (80 cols)
#define IMPITCH 78             // intermediate pitch (conflict-free h-pass phases)
#define IM_PLANE (TILE_H * IMPITCH)
#define NMAPS 4
#define GRID_X 8               // 512/64
#define GRID_Y 32              // 512/16
#define NBLOCKS (GRID_X * GRID_Y * NC)   // 12288
#define NPIX (16.0 * 3.0 * 512.0 * 512.0)

#define SS_OFF 0
#define SD_OFF (SH * SPITCH)                      // 2080 floats
#define IM_OFF (2 * SH * SPITCH)                  // 4160 floats
#define SMEM_FLOATS (IM_OFF + NMAPS * IM_PLANE)   // 4160 + 4992 = 9152
#define SMEM_BYTES (SMEM_FLOATS * 4)              // 36608 B -> 6 blocks/SM

// v-pass: column pairs p = 1..38 (im cols s=2..77), 8 row-groups of 2 rows
#define NVT (38 * 8)           // 304 tasks

// gaussian(11, sigma=1.5), normalized
#define W0 0.001028380f
#define W1 0.007598758f
#define W2 0.036000773f
#define W3 0.109360702f
#define W4 0.213005530f
#define W5 0.266011730f

__device__ float g_accum;            // zero at module load; reset by last block
__device__ unsigned int g_count;     // zero at module load; reset by last block

__device__ __forceinline__ float wt(int k) {
    switch (k) {
        case 0:  return W0;
        case 1:  return W1;
        case 2:  return W2;
        case 3:  return W3;
        case 4:  return W4;
        case 5:  return W5;
        case 6:  return W4;
        case 7:  return W3;
        case 8:  return W2;
        case 9:  return W1;
        default: return W0;
    }
}

// ---- packed f32x2 helpers (sm_103a) ----
__device__ __forceinline__ uint64_t pk2(float lo, float hi) {
    uint64_t r;
    asm("mov.b64 %0, {%1, %2};" : "=l"(r) : "f"(lo), "f"(hi));
    return r;
}
__device__ __forceinline__ void upk2(float& lo, float& hi, uint64_t v) {
    asm("mov.b64 {%0, %1}, %2;" : "=f"(lo), "=f"(hi) : "l"(v));
}
__device__ __forceinline__ float lo2(uint64_t v) { float a, b; upk2(a, b, v); return a; }
__device__ __forceinline__ float hi2(uint64_t v) { float a, b; upk2(a, b, v); return b; }
__device__ __forceinline__ uint64_t mul2(uint64_t a, uint64_t b) {
    uint64_t d;
    asm("mul.rn.f32x2 %0, %1, %2;" : "=l"(d) : "l"(a), "l"(b));
    return d;
}
__device__ __forceinline__ void fma2(uint64_t& d, uint64_t a, uint64_t b) {
    asm("fma.rn.f32x2 %0, %1, %2, %0;" : "+l"(d) : "l"(a), "l"(b));
}
__device__ __forceinline__ uint64_t wpair(int k) {
    float w = wt(k);
    return pk2(w, w);   // ptxas CSEs the 6 unique values
}

// One v-pass task: 4 maps (A=conv S, B=conv D, C=conv S^2, Dm=conv D^2),
// 2 output rows, one column pair. Reads 12 rows of ss+sd exactly once.
__device__ __forceinline__ void vtask(int t, const float* ss, float* im)
{
    const int p  = 1 + (t % 38);
    const int rg = t / 38;             // 0..7
    const int r0 = 2 * rg;
    const float* base = ss + r0 * SPITCH + 2 * p;   // sd at +SD_OFF

    uint64_t mA[2] = {0, 0}, mB[2] = {0, 0};
    uint64_t mC[2] = {0, 0}, mD[2] = {0, 0};

    #pragma unroll
    for (int rr = 0; rr < 12; ++rr) {
        uint64_t S = *(const uint64_t*)&base[rr * SPITCH];
        uint64_t D = *(const uint64_t*)&base[rr * SPITCH + SD_OFF];
        uint64_t S2 = mul2(S, S);
        uint64_t D2 = mul2(D, D);
        #pragma unroll
        for (int o = 0; o < 2; ++o) {
            const int k = rr - o;
            if (k >= 0 && k < 11) {
                const uint64_t w = wpair(k);
                fma2(mA[o], w, S);
                fma2(mB[o], w, D);
                fma2(mC[o], w, S2);
                fma2(mD[o], w, D2);
            }
        }
    }
    const int obase = r0 * IMPITCH + 2 * p;
    #pragma unroll
    for (int o = 0; o < 2; ++o) {
        *(uint64_t*)&im[0*IM_PLANE + obase + o*IMPITCH] = mA[o];
        *(uint64_t*)&im[1*IM_PLANE + obase + o*IMPITCH] = mB[o];
        *(uint64_t*)&im[2*IM_PLANE + obase + o*IMPITCH] = mC[o];
        *(uint64_t*)&im[3*IM_PLANE + obase + o*IMPITCH] = mD[o];
    }
}

__global__ void __launch_bounds__(256, 6) ssim_main(
    const float* __restrict__ pred, const float* __restrict__ targ,
    float* __restrict__ out)
{
    extern __shared__ float smem[];
    float* ss = smem + SS_OFF;   // S = pred + targ  (halo tile)
    float* sd = smem + SD_OFF;   // D = pred - targ
    float* im = smem + IM_OFF;   // 4 planes of IM_PLANE floats, pitch 78
    __shared__ float wsum[8];

    const int tid = threadIdx.x;
    const int z = blockIdx.z;
    const float* __restrict__ pbase = pred + (size_t)z * PLANE;
    const float* __restrict__ tbase = targ + (size_t)z * PLANE;
    const int gx0 = blockIdx.x * TILE_W - 8;   // 16B-aligned frame
    const int gy0 = blockIdx.y * TILE_H - 5;

    // ---- load halo tile as float4 quads, store S/D (zero pad) ----
    for (int i = tid; i < SH * NQUADS; i += 256) {
        int r = i / NQUADS;
        int q = i - r * NQUADS;
        int gr = gy0 + r;
        int gc = gx0 + 4 * q;
        float4 sv = make_float4(0.f, 0.f, 0.f, 0.f);
        float4 dv = make_float4(0.f, 0.f, 0.f, 0.f);
        if ((unsigned)gr < (unsigned)HH && (unsigned)gc < (unsigned)WW) {
            size_t off = (size_t)gr * WW + gc;
            float4 pv = *(const float4*)(pbase + off);
            float4 tv = *(const float4*)(tbase + off);
            sv = make_float4(pv.x + tv.x, pv.y + tv.y, pv.z + tv.z, pv.w + tv.w);
            dv = make_float4(pv.x - tv.x, pv.y - tv.y, pv.z - tv.z, pv.w - tv.w);
        }
        *(float4*)&ss[r * SPITCH + 4 * q] = sv;
        *(float4*)&sd[r * SPITCH + 4 * q] = dv;
    }
    __syncthreads();

    // ---- vertical pass: 304 tasks over 256 threads ----
    vtask(tid, ss, im);
    if (tid < NVT - 256)
        vtask(256 + tid, ss, im);
    __syncthreads();

    // ---- horizontal pass + SSIM (rolling-pair streaming) ----
    // Output col j (tile frame): taps at im col s = j+3+k, k=0..10.
    // 16 rows x 16 col-groups (4 cols = 2 output pairs) = exactly 256 tasks.
    float lsum = 0.f;
    {
        const int w = tid >> 5;
        const int l = tid & 31;
        const int row = 2 * w + ((l >> 3) & 1);
        const int cg  = (l & 7) | ((l >> 4) << 3);
        const int j0 = 4 * cg;
        const int rbase = row * IMPITCH + j0 + 2;   // even -> 8B aligned

        float res[NMAPS][4];

        #pragma unroll
        for (int m = 0; m < NMAPS; ++m) {
            uint64_t acc0 = 0, acc1 = 0;   // outputs (j0,j0+1), (j0+2,j0+3)
            uint64_t eprev = 0;
            #pragma unroll
            for (int i = 0; i < 8; ++i) {
                uint64_t ecur = *(const uint64_t*)&im[m * IM_PLANE + rbase + 2 * i];
                if (i > 0) {
                    // od_{i-1}: pair starting at s = j0+1+2i
                    uint64_t od = pk2(hi2(eprev), lo2(ecur));
                    if (i <= 6)            fma2(acc0, wpair(2*i - 2), od);
                    if (i >= 2)            fma2(acc1, wpair(2*i - 4), od);
                }
                // e_i: pair starting at s = j0+2+2i
                if (i >= 1 && i <= 5)      fma2(acc0, wpair(2*i - 1), ecur);
                if (i >= 2 && i <= 6)      fma2(acc1, wpair(2*i - 3), ecur);
                eprev = ecur;
            }
            upk2(res[m][0], res[m][1], acc0);
            upk2(res[m][2], res[m][3], acc1);
        }

        const float C1 = 1e-4f;
        const float C2 = 9e-4f;
        #pragma unroll
        for (int h = 0; h < 4; ++h) {
            float A  = res[0][h], B  = res[1][h];
            float Cm = res[2][h], Dm = res[3][h];
            float A2 = A * A;
            float B2 = B * B;
            float U  = A2 - B2;           // = 4 mu_xy
            float V  = A2 + B2;           // = 2 (mu_x^2 + mu_y^2)
            float n1 = fmaf(0.5f, U, C1);               // 2 mu_xy + C1
            float n2 = fmaf(0.5f, (Cm - Dm) - U, C2);   // 2 sg_xy + C2
            float d1 = fmaf(0.5f, V, C1);               // mu_x^2+mu_y^2 + C1
            float d2 = fmaf(0.5f, (Cm + Dm) - V, C2);   // sg_x+sg_y + C2
            lsum += __fdividef(n1 * n2, d1 * d2);
        }
    }

    // ---- block reduction ----
    #pragma unroll
    for (int s = 16; s > 0; s >>= 1)
        lsum += __shfl_xor_sync(0xffffffffu, lsum, s);
    if ((tid & 31) == 0) wsum[tid >> 5] = lsum;
    __syncthreads();

    // ---- global accumulate + last-block finalize ----
    if (tid == 0) {
        float bs = 0.f;
        #pragma unroll
        for (int i = 0; i < 8; ++i) bs += wsum[i];
        atomicAdd(&g_accum, bs);
        __threadfence();
        unsigned int prev = atomicAdd(&g_count, 1u);
        if (prev == NBLOCKS - 1) {
            float s = g_accum;
            out[0] = (float)(1.0 - (double)s / NPIX);
            g_accum = 0.f;          // reset for next graph replay
            g_count = 0u;
        }
    }
}

extern "C" void kernel_launch(void* const* d_in, const int* in_sizes, int n_in,
                              void* d_out, int out_size)
{
    (void)in_sizes; (void)n_in; (void)out_size;
    const float* pred = (const float*)d_in[0];
    const float* targ = (const float*)d_in[1];

    dim3 grid(GRID_X, GRID_Y, NC);
    ssim_main<<<grid, 256, SMEM_BYTES>>>(pred, targ, (float*)d_out);
}